// round 15
// baseline (speedup 1.0000x reference)
#include <cuda_runtime.h>
#include <cuda_fp16.h>
#include <cstdint>

#define NUM_CODES 512
#define DIMS      64
#define HT        4096
#define N_VEC     131072
#define ZQ_SIZE   8388608
#define CTA_M     128
#define THREADS   256
#define GRID      148
#define NTILES    1024

// ---- dynamic smem layout (bytes), MMA regions 1024-aligned for SW128 ----
#define SM_AHI   0
#define SM_ALO   16384
#define SM_BHI   32768
#define SM_BLO   98304
#define SM_WSUM  163840
#define SM_RED   163904          // 512 floats for in-kernel finalize
#define SMEM_TOTAL 165952

__device__ float g_part[GRID];        // zero-init; overwritten every call
__device__ int   g_counts[NUM_CODES]; // zero-init; reset by finalize branch
__device__ int   g_done;              // zero-init; reset by finalize branch

#define SW(x) ((x) ^ ((((uint32_t)(x)) >> 3) & 0x70))

__device__ __forceinline__ uint32_t smem_u32(const void* p) {
    uint32_t a;
    asm("{ .reg .u64 t; cvta.to.shared.u64 t, %1; cvt.u32.u64 %0, t; }" : "=r"(a) : "l"(p));
    return a;
}
__device__ __forceinline__ void ldsm_x4(uint32_t& r0, uint32_t& r1, uint32_t& r2, uint32_t& r3, uint32_t a) {
    asm volatile("ldmatrix.sync.aligned.m8n8.x4.shared.b16 {%0,%1,%2,%3}, [%4];"
                 : "=r"(r0), "=r"(r1), "=r"(r2), "=r"(r3) : "r"(a));
}
__device__ __forceinline__ void mma16816(float* c, const uint32_t* a, uint32_t b0, uint32_t b1) {
    asm volatile("mma.sync.aligned.m16n8k16.row.col.f32.f16.f16.f32 "
                 "{%0,%1,%2,%3}, {%4,%5,%6,%7}, {%8,%9}, {%0,%1,%2,%3};"
                 : "+f"(c[0]), "+f"(c[1]), "+f"(c[2]), "+f"(c[3])
                 : "r"(a[0]), "r"(a[1]), "r"(a[2]), "r"(a[3]), "r"(b0), "r"(b1));
}
__device__ __forceinline__ uint32_t h2u(__half2 h) { return reinterpret_cast<uint32_t&>(h); }
__device__ __forceinline__ float2   u2f(uint32_t u) { __half2 h = reinterpret_cast<__half2&>(u); return __half22float2(h); }

__global__ __launch_bounds__(THREADS, 1) void vq_main(
    const float* __restrict__ z_e, const float* __restrict__ embed,
    float* __restrict__ out)
{
    extern __shared__ char smem[];
    const uint32_t sbase = smem_u32(smem);
    const int tid = threadIdx.x, wid = tid >> 5, lid = tid & 31;

    // ---------- B fill ONCE: embedding (512x64 fp32) -> f16 hi/lo, SW128 ----------
    {
        const float4* e4 = (const float4*)embed;
        #pragma unroll 8
        for (int i = tid; i < NUM_CODES * DIMS / 4; i += THREADS) {
            float4 f = e4[i];
            int row = i >> 4, dg = i & 15;
            __half hx = __float2half_rn(f.x), hy = __float2half_rn(f.y);
            __half hz = __float2half_rn(f.z), hw = __float2half_rn(f.w);
            __half lx = __float2half_rn(f.x - __half2float(hx));
            __half ly = __float2half_rn(f.y - __half2float(hy));
            __half lz = __float2half_rn(f.z - __half2float(hz));
            __half lw = __float2half_rn(f.w - __half2float(hw));
            uint32_t off = SW(row * 128 + dg * 8);
            *(uint2*)(smem + SM_BHI + off) = make_uint2(h2u(__halves2half2(hx, hy)), h2u(__halves2half2(hz, hw)));
            *(uint2*)(smem + SM_BLO + off) = make_uint2(h2u(__halves2half2(lx, ly)), h2u(__halves2half2(lz, lw)));
        }
    }

    const int rbase = wid * 16;              // one m-tile (16 rows) per warp
    const int arow = tid >> 1;               // A-fill / epilogue: half row per thread
    const int ahalf = tid & 1;               // dims [ahalf*32, ahalf*32+32)
    const uint32_t brow = ((lid >> 4) << 3) + (lid & 7);
    const uint32_t bk_off = ((lid >> 3) & 1) << 4;
    const int kb = 2 * (lid & 3);
    float csum_total = 0.f;

    // ---------- prefetch first tile's z (half row) into registers ----------
    float zraw[16], zraw2[16];
    {
        const int n0 = blockIdx.x * CTA_M + arow;
        const int b0 = n0 >> 12, r0 = n0 & 4095;
        const float* zp0 = z_e + (size_t)b0 * (DIMS * HT) + r0 + (size_t)(ahalf * 32) * HT;
        #pragma unroll
        for (int d = 0; d < 16; d++) {
            zraw[d]  = zp0[(size_t)(2 * d) * HT];
            zraw2[d] = zp0[(size_t)(2 * d + 1) * HT];
        }
    }

    // ================= persistent tile loop =================
    for (int tile = blockIdx.x; tile < NTILES; tile += GRID) {
        const int n = tile * CTA_M + arow;
        const int b = n >> 12, r = n & 4095;

        // ---------- A fill from registers -> f16 hi/lo, SW128 ----------
        #pragma unroll
        for (int i = 0; i < 4; i++) {
            uint32_t zh[4], zl[4];
            #pragma unroll
            for (int j = 0; j < 4; j++) {
                float x0 = zraw[4 * i + j];
                float x1 = zraw2[4 * i + j];
                __half h0 = __float2half_rn(x0), h1 = __float2half_rn(x1);
                __half l0 = __float2half_rn(x0 - __half2float(h0));
                __half l1 = __float2half_rn(x1 - __half2float(h1));
                zh[j] = h2u(__halves2half2(h0, h1));
                zl[j] = h2u(__halves2half2(l0, l1));
            }
            uint32_t off = SW(arow * 128 + ahalf * 64 + i * 16);
            *(uint4*)(smem + SM_AHI + off) = make_uint4(zh[0], zh[1], zh[2], zh[3]);
            *(uint4*)(smem + SM_ALO + off) = make_uint4(zl[0], zl[1], zl[2], zl[3]);
        }
        __syncthreads();   // A (and on iter 0, B) ready

        // ---------- A hi fragments only (2-pass: z_hi * (e_hi + e_lo)) ----------
        uint32_t a_hi[4][4];
        {
            uint32_t row = rbase + ((lid >> 3) & 1) * 8 + (lid & 7);
            uint32_t cg  = (lid >> 4) << 4;
            #pragma unroll
            for (int kt = 0; kt < 4; kt++) {
                uint32_t sw = SW(row * 128 + kt * 32 + cg);
                ldsm_x4(a_hi[kt][0], a_hi[kt][1], a_hi[kt][2], a_hi[kt][3], sbase + SM_AHI + sw);
            }
        }

        // ---------- main loop: double-buffered acc, top-3 tracking per slot ----------
        float v1[2] = {-3.4e38f, -3.4e38f}, v2[2] = {-3.4e38f, -3.4e38f}, v3[2] = {-3.4e38f, -3.4e38f};
        int   kk1[2] = {0, 0}, kk2[2] = {0, 0}, kk3[2] = {0, 0};
        float acc0[2][4], acc1[2][4];

#define ZEROACC(A)                                                                 \
        { _Pragma("unroll") for (int h = 0; h < 2; h++)                            \
          _Pragma("unroll") for (int i = 0; i < 4; i++) (A)[h][i] = 0.f; }

#define DOMMA(A, NTP)                                                              \
        { uint32_t B[4][8];                                                        \
          _Pragma("unroll")                                                        \
          for (int kt = 0; kt < 4; kt++) {                                         \
              uint32_t sw = SW((uint32_t)(((NTP) * 16 + brow) * 128 + kt * 32 + bk_off)); \
              ldsm_x4(B[kt][0], B[kt][1], B[kt][2], B[kt][3], sbase + SM_BHI + sw);\
              ldsm_x4(B[kt][4], B[kt][5], B[kt][6], B[kt][7], sbase + SM_BLO + sw);\
          }                                                                        \
          _Pragma("unroll")                                                        \
          for (int kt = 0; kt < 4; kt++) {                                         \
              mma16816((A)[0], a_hi[kt], B[kt][0], B[kt][1]);                      \
              mma16816((A)[1], a_hi[kt], B[kt][2], B[kt][3]);                      \
              mma16816((A)[0], a_hi[kt], B[kt][4], B[kt][5]);                      \
              mma16816((A)[1], a_hi[kt], B[kt][6], B[kt][7]);                      \
          } }

        // top-3 insertion per slot; values arrive in ascending-k order within slot,
        // strict > keeps earliest k on approx ties
#define TRACK3(A, NTP)                                                             \
        { const int kbase = (NTP) * 16 + kb;                                       \
          _Pragma("unroll") for (int h = 0; h < 2; h++)                            \
          _Pragma("unroll") for (int i = 0; i < 4; i++) {                          \
              int s = i >> 1;                                                      \
              int k = kbase + h * 8 + (i & 1);                                     \
              float dot = (A)[h][i];                                               \
              if (dot > v3[s]) {                                                   \
                  if (dot > v2[s]) {                                               \
                      if (dot > v1[s]) {                                           \
                          v3[s] = v2[s]; kk3[s] = kk2[s];                          \
                          v2[s] = v1[s]; kk2[s] = kk1[s];                          \
                          v1[s] = dot;   kk1[s] = k;                               \
                      } else {                                                     \
                          v3[s] = v2[s]; kk3[s] = kk2[s];                          \
                          v2[s] = dot;   kk2[s] = k;                               \
                      }                                                            \
                  } else { v3[s] = dot; kk3[s] = k; }                              \
              }                                                                    \
          } }

        ZEROACC(acc0);
        DOMMA(acc0, 0);
        #pragma unroll 2
        for (int ntpp = 0; ntpp < 15; ntpp++) {
            const int e = 2 * ntpp;
            ZEROACC(acc1);
            DOMMA(acc1, e + 1);
            TRACK3(acc0, e);
            ZEROACC(acc0);
            DOMMA(acc0, e + 2);
            TRACK3(acc1, e + 1);
        }
        ZEROACC(acc1);
        DOMMA(acc1, 31);
        TRACK3(acc0, 30);
        TRACK3(acc1, 31);

        // ---------- issue next tile's z LDGs (overlap with rescue/epilogue) ----------
        {
            int ntile = tile + GRID;
            if (ntile >= NTILES) ntile = tile;       // dummy valid address
            const int nn = ntile * CTA_M + arow;
            const int nb = nn >> 12, nr = nn & 4095;
            const float* znp = z_e + (size_t)nb * (DIMS * HT) + nr + (size_t)(ahalf * 32) * HT;
            #pragma unroll
            for (int d = 0; d < 16; d++) {
                zraw[d]  = __ldg(znp + (size_t)(2 * d) * HT);
                zraw2[d] = __ldg(znp + (size_t)(2 * d + 1) * HT);
            }
        }

        // ---------- exact fp32 rescue: recompute 3 candidates per slot ----------
        float best_d[2]; int best_k[2];
        #pragma unroll
        for (int s = 0; s < 2; s++) {
            const int zrow = rbase + s * 8 + (lid >> 2);
            const int c0 = kk1[s], c1 = kk2[s], c2 = kk3[s];
            float d0 = 0.f, d1 = 0.f, d2 = 0.f;
            #pragma unroll
            for (int dg = 0; dg < 16; dg++) {
                uint32_t zo = SW(zrow * 128 + dg * 8);
                uint2 zh = *(uint2*)(smem + SM_AHI + zo);
                uint2 zl = *(uint2*)(smem + SM_ALO + zo);
                float2 za = u2f(zh.x), zb = u2f(zl.x), zc = u2f(zh.y), zd = u2f(zl.y);
                float zv0 = za.x + zb.x, zv1 = za.y + zb.y, zv2 = zc.x + zd.x, zv3 = zc.y + zd.y;
                uint32_t o0 = SW(c0 * 128 + dg * 8);
                uint32_t o1 = SW(c1 * 128 + dg * 8);
                uint32_t o2 = SW(c2 * 128 + dg * 8);
                uint2 h0v = *(uint2*)(smem + SM_BHI + o0), l0v = *(uint2*)(smem + SM_BLO + o0);
                uint2 h1v = *(uint2*)(smem + SM_BHI + o1), l1v = *(uint2*)(smem + SM_BLO + o1);
                uint2 h2v = *(uint2*)(smem + SM_BHI + o2), l2v = *(uint2*)(smem + SM_BLO + o2);
                float2 a0 = u2f(h0v.x), b0 = u2f(l0v.x), e0 = u2f(h0v.y), f0 = u2f(l0v.y);
                float2 a1 = u2f(h1v.x), b1 = u2f(l1v.x), e1 = u2f(h1v.y), f1 = u2f(l1v.y);
                float2 a2 = u2f(h2v.x), b2 = u2f(l2v.x), e2 = u2f(h2v.y), f2 = u2f(l2v.y);
                d0 += zv0 * (a0.x + b0.x) + zv1 * (a0.y + b0.y) + zv2 * (e0.x + f0.x) + zv3 * (e0.y + f0.y);
                d1 += zv0 * (a1.x + b1.x) + zv1 * (a1.y + b1.y) + zv2 * (e1.x + f1.x) + zv3 * (e1.y + f1.y);
                d2 += zv0 * (a2.x + b2.x) + zv1 * (a2.y + b2.y) + zv2 * (e2.x + f2.x) + zv3 * (e2.y + f2.y);
            }
            float bd = d0; int bk = c0;
            if (d1 > bd || (d1 == bd && c1 < bk)) { bd = d1; bk = c1; }
            if (d2 > bd || (d2 == bd && c2 < bk)) { bd = d2; bk = c2; }
            best_d[s] = bd; best_k[s] = bk;
        }

        // ---------- merge exact best across the 4 quad lanes ----------
        #pragma unroll
        for (int off = 1; off <= 2; off <<= 1) {
            #pragma unroll
            for (int s = 0; s < 2; s++) {
                float od = __shfl_xor_sync(0xffffffffu, best_d[s], off);
                int   ok = __shfl_xor_sync(0xffffffffu, best_k[s], off);
                if (od > best_d[s] || (od == best_d[s] && ok < best_k[s])) {
                    best_d[s] = od; best_k[s] = ok;
                }
            }
        }
        // distribute bi to this thread's row (same warp owns it)
        int bi;
        {
            const int rr = (tid >> 1) & 15;
            const int src = 4 * (rr & 7);
            int w0 = __shfl_sync(0xffffffffu, best_k[0], src);
            int w1 = __shfl_sync(0xffffffffu, best_k[1], src);
            bi = (rr >> 3) ? w1 : w0;
        }

        // ---------- outputs (half-row per thread) ----------
        float* op = out + (size_t)b * (DIMS * HT) + r + (size_t)(ahalf * 32) * HT;
        float csum = 0.f;
        #pragma unroll
        for (int dg = 0; dg < 8; dg++) {
            uint32_t zo = SW(arow * 128 + ahalf * 64 + dg * 8);
            uint2 zh = *(uint2*)(smem + SM_AHI + zo);
            uint2 zl = *(uint2*)(smem + SM_ALO + zo);
            float2 z01 = u2f(zh.x), zl01 = u2f(zl.x), z23 = u2f(zh.y), zl23 = u2f(zl.y);
            float zv0 = z01.x + zl01.x, zv1 = z01.y + zl01.y;
            float zv2 = z23.x + zl23.x, zv3 = z23.y + zl23.y;
            uint32_t qo = SW(bi * 128 + ahalf * 64 + dg * 8);
            uint2 qh = *(uint2*)(smem + SM_BHI + qo);
            uint2 ql = *(uint2*)(smem + SM_BLO + qo);
            float2 e01 = u2f(qh.x), el01 = u2f(ql.x), e23 = u2f(qh.y), el23 = u2f(ql.y);
            float q0 = e01.x + el01.x, q1 = e01.y + el01.y, q2 = e23.x + el23.x, q3 = e23.y + el23.y;
            float d0 = q0 - zv0, d1v = q1 - zv1, d2v = q2 - zv2, d3 = q3 - zv3;
            op[(4 * dg + 0) * HT] = zv0 + d0;
            op[(4 * dg + 1) * HT] = zv1 + d1v;
            op[(4 * dg + 2) * HT] = zv2 + d2v;
            op[(4 * dg + 3) * HT] = zv3 + d3;
            csum += d0 * d0 + d1v * d1v + d2v * d2v + d3 * d3;
        }
        if (ahalf == 0) {
            out[ZQ_SIZE + 1 + n] = (float)bi;
            atomicAdd(&g_counts[bi], 1);
        }
        csum_total += csum;

        __syncthreads();   // protect A smem before next tile's A-fill
    }

    // ---------- per-CTA commitment partial ----------
    #pragma unroll
    for (int off = 16; off; off >>= 1)
        csum_total += __shfl_down_sync(0xffffffffu, csum_total, off);
    float* wsum = (float*)(smem + SM_WSUM);
    if (lid == 0) wsum[wid] = csum_total;
    __syncthreads();
    if (tid == 0) {
        float s = 0.f;
        #pragma unroll
        for (int w = 0; w < 8; w++) s += wsum[w];
        g_part[blockIdx.x] = s;
    }

    // ---------- last-CTA in-kernel finalize ----------
    __threadfence();
    __shared__ int s_last;
    if (tid == 0) s_last = (atomicAdd(&g_done, 1) == GRID - 1);
    __syncthreads();
    if (s_last) {
        __threadfence();
        float* red = (float*)(smem + SM_RED);

        // commitment
        red[tid] = (tid < GRID) ? g_part[tid] : 0.f;
        __syncthreads();
        #pragma unroll
        for (int off = 128; off; off >>= 1) {
            if (tid < off) red[tid] += red[tid + off];
            __syncthreads();
        }
        if (tid == 0) out[ZQ_SIZE] = 0.25f * red[0] / (float)ZQ_SIZE;
        __syncthreads();

        // entropy -> perplexity (512 codes, 2 per thread)
        const int c0 = g_counts[tid], c1 = g_counts[tid + 256];
        {
            float p0 = (float)c0 / (float)N_VEC, p1 = (float)c1 / (float)N_VEC;
            red[tid] = -p0 * logf(p0 + 1e-12f) - p1 * logf(p1 + 1e-12f);
        }
        __syncthreads();
        #pragma unroll
        for (int off = 128; off; off >>= 1) {
            if (tid < off) red[tid] += red[tid + off];
            __syncthreads();
        }
        if (tid == 0) out[ZQ_SIZE + 1 + N_VEC] = expf(red[0]);
        __syncthreads();

        // usage
        red[tid] = ((c0 > 0) ? 1.f : 0.f) + ((c1 > 0) ? 1.f : 0.f);
        __syncthreads();
        #pragma unroll
        for (int off = 128; off; off >>= 1) {
            if (tid < off) red[tid] += red[tid + off];
            __syncthreads();
        }
        if (tid == 0) out[ZQ_SIZE + 1 + N_VEC + 1] = red[0] / (float)NUM_CODES;

        // reset state for next graph replay
        g_counts[tid] = 0;
        g_counts[tid + 256] = 0;
        if (tid == 0) g_done = 0;
    }
}

extern "C" void kernel_launch(void* const* d_in, const int* in_sizes, int n_in,
                              void* d_out, int out_size) {
    const float* z_e   = (const float*)d_in[0];
    const float* embed = (const float*)d_in[1];
    float* out = (float*)d_out;

    cudaFuncSetAttribute(vq_main, cudaFuncAttributeMaxDynamicSharedMemorySize, SMEM_TOTAL);
    vq_main<<<GRID, THREADS, SMEM_TOTAL>>>(z_e, embed, out);
}

// round 16
// speedup vs baseline: 2.1083x; 2.1083x over previous
#include <cuda_runtime.h>
#include <cuda_fp16.h>
#include <cstdint>

#define NUM_CODES 512
#define DIMS      64
#define HT        4096
#define N_VEC     131072
#define ZQ_SIZE   8388608
#define CTA_M     128
#define THREADS   256
#define GRID      148
#define NTILES    1024

// ---- dynamic smem layout (bytes), MMA regions 1024-aligned for SW128 ----
// A double-buffered: tile parity selects buffer (removes trailing sync)
#define SM_AHI0  0
#define SM_ALO0  16384
#define SM_AHI1  32768
#define SM_ALO1  49152
#define SM_BHI   65536
#define SM_BLO   131072
#define SM_WSUM  196608
#define SM_RED   196672          // 512 floats for in-kernel finalize
#define SMEM_TOTAL 198720

__device__ float g_part[GRID];        // zero-init; overwritten every call
__device__ int   g_counts[NUM_CODES]; // zero-init; reset by finalize branch
__device__ int   g_done;              // zero-init; reset by finalize branch

#define SW(x) ((x) ^ ((((uint32_t)(x)) >> 3) & 0x70))

__device__ __forceinline__ uint32_t smem_u32(const void* p) {
    uint32_t a;
    asm("{ .reg .u64 t; cvta.to.shared.u64 t, %1; cvt.u32.u64 %0, t; }" : "=r"(a) : "l"(p));
    return a;
}
__device__ __forceinline__ void ldsm_x4(uint32_t& r0, uint32_t& r1, uint32_t& r2, uint32_t& r3, uint32_t a) {
    asm volatile("ldmatrix.sync.aligned.m8n8.x4.shared.b16 {%0,%1,%2,%3}, [%4];"
                 : "=r"(r0), "=r"(r1), "=r"(r2), "=r"(r3) : "r"(a));
}
__device__ __forceinline__ void mma16816(float* c, const uint32_t* a, uint32_t b0, uint32_t b1) {
    asm volatile("mma.sync.aligned.m16n8k16.row.col.f32.f16.f16.f32 "
                 "{%0,%1,%2,%3}, {%4,%5,%6,%7}, {%8,%9}, {%0,%1,%2,%3};"
                 : "+f"(c[0]), "+f"(c[1]), "+f"(c[2]), "+f"(c[3])
                 : "r"(a[0]), "r"(a[1]), "r"(a[2]), "r"(a[3]), "r"(b0), "r"(b1));
}
__device__ __forceinline__ uint32_t h2u(__half2 h) { return reinterpret_cast<uint32_t&>(h); }
__device__ __forceinline__ float2   u2f(uint32_t u) { __half2 h = reinterpret_cast<__half2&>(u); return __half22float2(h); }

__global__ __launch_bounds__(THREADS, 1) void vq_main(
    const float* __restrict__ z_e, const float* __restrict__ embed,
    float* __restrict__ out)
{
    extern __shared__ char smem[];
    const uint32_t sbase = smem_u32(smem);
    const int tid = threadIdx.x, wid = tid >> 5, lid = tid & 31;

    // ---------- B fill ONCE: embedding (512x64 fp32) -> f16 hi/lo, SW128 ----------
    {
        const float4* e4 = (const float4*)embed;
        #pragma unroll 8
        for (int i = tid; i < NUM_CODES * DIMS / 4; i += THREADS) {
            float4 f = e4[i];
            int row = i >> 4, dg = i & 15;
            __half hx = __float2half_rn(f.x), hy = __float2half_rn(f.y);
            __half hz = __float2half_rn(f.z), hw = __float2half_rn(f.w);
            __half lx = __float2half_rn(f.x - __half2float(hx));
            __half ly = __float2half_rn(f.y - __half2float(hy));
            __half lz = __float2half_rn(f.z - __half2float(hz));
            __half lw = __float2half_rn(f.w - __half2float(hw));
            uint32_t off = SW(row * 128 + dg * 8);
            *(uint2*)(smem + SM_BHI + off) = make_uint2(h2u(__halves2half2(hx, hy)), h2u(__halves2half2(hz, hw)));
            *(uint2*)(smem + SM_BLO + off) = make_uint2(h2u(__halves2half2(lx, ly)), h2u(__halves2half2(lz, lw)));
        }
    }

    const int rbase = wid * 16;              // one m-tile (16 rows) per warp
    const int arow = tid >> 1;               // A-fill / epilogue: half row per thread
    const int ahalf = tid & 1;               // dims [ahalf*32, ahalf*32+32)
    const uint32_t brow = ((lid >> 4) << 3) + (lid & 7);
    const uint32_t bk_off = ((lid >> 3) & 1) << 4;
    const int kb = 2 * (lid & 3);
    float csum_total = 0.f;
    int pbuf = 0;

    // ---------- prefetch first tile's z (half row) into registers ----------
    float zraw[16], zraw2[16];
    {
        const int n0 = blockIdx.x * CTA_M + arow;
        const int b0 = n0 >> 12, r0 = n0 & 4095;
        const float* zp0 = z_e + (size_t)b0 * (DIMS * HT) + r0 + (size_t)(ahalf * 32) * HT;
        #pragma unroll
        for (int d = 0; d < 16; d++) {
            zraw[d]  = zp0[(size_t)(2 * d) * HT];
            zraw2[d] = zp0[(size_t)(2 * d + 1) * HT];
        }
    }

    // ================= persistent tile loop =================
    for (int tile = blockIdx.x; tile < NTILES; tile += GRID) {
        const int n = tile * CTA_M + arow;
        const int b = n >> 12, r = n & 4095;
        const uint32_t ahi = pbuf ? SM_AHI1 : SM_AHI0;
        const uint32_t alo = pbuf ? SM_ALO1 : SM_ALO0;

        // ---------- A fill from registers -> f16 hi/lo, SW128 ----------
        #pragma unroll
        for (int i = 0; i < 4; i++) {
            uint32_t zh[4], zl[4];
            #pragma unroll
            for (int j = 0; j < 4; j++) {
                float x0 = zraw[4 * i + j];
                float x1 = zraw2[4 * i + j];
                __half h0 = __float2half_rn(x0), h1 = __float2half_rn(x1);
                __half l0 = __float2half_rn(x0 - __half2float(h0));
                __half l1 = __float2half_rn(x1 - __half2float(h1));
                zh[j] = h2u(__halves2half2(h0, h1));
                zl[j] = h2u(__halves2half2(l0, l1));
            }
            uint32_t off = SW(arow * 128 + ahalf * 64 + i * 16);
            *(uint4*)(smem + ahi + off) = make_uint4(zh[0], zh[1], zh[2], zh[3]);
            *(uint4*)(smem + alo + off) = make_uint4(zl[0], zl[1], zl[2], zl[3]);
        }
        __syncthreads();   // A buffer (and on iter 0, B) ready; also fences prior epilogue reads

        // ---------- A fragments (1 m-tile per warp) ----------
        uint32_t a_hi[4][4], a_lo[4][4];
        {
            uint32_t row = rbase + ((lid >> 3) & 1) * 8 + (lid & 7);
            uint32_t cg  = (lid >> 4) << 4;
            #pragma unroll
            for (int kt = 0; kt < 4; kt++) {
                uint32_t sw = SW(row * 128 + kt * 32 + cg);
                ldsm_x4(a_hi[kt][0], a_hi[kt][1], a_hi[kt][2], a_hi[kt][3], sbase + ahi + sw);
                ldsm_x4(a_lo[kt][0], a_lo[kt][1], a_lo[kt][2], a_lo[kt][3], sbase + alo + sw);
            }
        }

        // ---------- main loop: double-buffered accumulators ----------
        float m1[2] = {-3.4e38f, -3.4e38f};
        int   i1[2] = {0, 0};
        float acc0[2][4], acc1[2][4];

#define ZEROACC(A)                                                                 \
        { _Pragma("unroll") for (int h = 0; h < 2; h++)                            \
          _Pragma("unroll") for (int i = 0; i < 4; i++) (A)[h][i] = 0.f; }

#define DOMMA(A, NTP)                                                              \
        { uint32_t B[4][8];                                                        \
          _Pragma("unroll")                                                        \
          for (int kt = 0; kt < 4; kt++) {                                         \
              uint32_t sw = SW((uint32_t)(((NTP) * 16 + brow) * 128 + kt * 32 + bk_off)); \
              ldsm_x4(B[kt][0], B[kt][1], B[kt][2], B[kt][3], sbase + SM_BHI + sw);\
              ldsm_x4(B[kt][4], B[kt][5], B[kt][6], B[kt][7], sbase + SM_BLO + sw);\
          }                                                                        \
          _Pragma("unroll")                                                        \
          for (int kt = 0; kt < 4; kt++) {                                         \
              mma16816((A)[0], a_hi[kt], B[kt][0], B[kt][1]);                      \
              mma16816((A)[1], a_hi[kt], B[kt][2], B[kt][3]);                      \
              mma16816((A)[0], a_hi[kt], B[kt][4], B[kt][5]);                      \
              mma16816((A)[1], a_hi[kt], B[kt][6], B[kt][7]);                      \
              mma16816((A)[0], a_lo[kt], B[kt][0], B[kt][1]);                      \
              mma16816((A)[1], a_lo[kt], B[kt][2], B[kt][3]);                      \
          } }

#define TRACK(A, NTP)                                                              \
        { const int kbase = (NTP) * 16 + kb;                                       \
          _Pragma("unroll") for (int h = 0; h < 2; h++)                            \
          _Pragma("unroll") for (int i = 0; i < 4; i++) {                          \
              int s = i >> 1;                                                      \
              int k = kbase + h * 8 + (i & 1);                                     \
              float dot = (A)[h][i];                                               \
              if (dot > m1[s]) { m1[s] = dot; i1[s] = k; }                         \
          } }

        ZEROACC(acc0);
        DOMMA(acc0, 0);
        #pragma unroll 2
        for (int ntpp = 0; ntpp < 15; ntpp++) {
            const int e = 2 * ntpp;
            ZEROACC(acc1);
            DOMMA(acc1, e + 1);
            TRACK(acc0, e);
            ZEROACC(acc0);
            DOMMA(acc0, e + 2);
            TRACK(acc1, e + 1);
        }
        ZEROACC(acc1);
        DOMMA(acc1, 31);
        TRACK(acc0, 30);
        TRACK(acc1, 31);

        // ---------- issue next tile's z LDGs (overlap with epilogue) ----------
        {
            int ntile = tile + GRID;
            if (ntile >= NTILES) ntile = tile;       // dummy valid address
            const int nn = ntile * CTA_M + arow;
            const int nb = nn >> 12, nr = nn & 4095;
            const float* znp = z_e + (size_t)nb * (DIMS * HT) + nr + (size_t)(ahalf * 32) * HT;
            #pragma unroll
            for (int d = 0; d < 16; d++) {
                zraw[d]  = __ldg(znp + (size_t)(2 * d) * HT);
                zraw2[d] = __ldg(znp + (size_t)(2 * d + 1) * HT);
            }
        }

        // ---------- merge max(dot) across the 4 quad lanes ----------
        #pragma unroll
        for (int off = 1; off <= 2; off <<= 1) {
            #pragma unroll
            for (int s = 0; s < 2; s++) {
                float om = __shfl_xor_sync(0xffffffffu, m1[s], off);
                int   oi = __shfl_xor_sync(0xffffffffu, i1[s], off);
                bool take = (om > m1[s]) || (om == m1[s] && oi < i1[s]);
                if (take) { m1[s] = om; i1[s] = oi; }
            }
        }
        // shuffle-based bi for this thread's row (same warp owns it)
        int bi;
        {
            const int rr = (tid >> 1) & 15;          // row within this warp's m-tile
            const int src = 4 * (rr & 7);
            int v0 = __shfl_sync(0xffffffffu, i1[0], src);
            int v1 = __shfl_sync(0xffffffffu, i1[1], src);
            bi = (rr >> 3) ? v1 : v0;
        }

        // ---------- outputs (half-row per thread) ----------
        float* op = out + (size_t)b * (DIMS * HT) + r + (size_t)(ahalf * 32) * HT;
        float csum = 0.f;
        #pragma unroll
        for (int dg = 0; dg < 8; dg++) {
            uint32_t zo = SW(arow * 128 + ahalf * 64 + dg * 8);
            uint2 zh = *(uint2*)(smem + ahi + zo);
            uint2 zl = *(uint2*)(smem + alo + zo);
            float2 z01 = u2f(zh.x), zl01 = u2f(zl.x), z23 = u2f(zh.y), zl23 = u2f(zl.y);
            float zv0 = z01.x + zl01.x, zv1 = z01.y + zl01.y;
            float zv2 = z23.x + zl23.x, zv3 = z23.y + zl23.y;
            uint32_t qo = SW(bi * 128 + ahalf * 64 + dg * 8);
            uint2 qh = *(uint2*)(smem + SM_BHI + qo);
            uint2 ql = *(uint2*)(smem + SM_BLO + qo);
            float2 e01 = u2f(qh.x), el01 = u2f(ql.x), e23 = u2f(qh.y), el23 = u2f(ql.y);
            float q0 = e01.x + el01.x, q1 = e01.y + el01.y, q2 = e23.x + el23.x, q3 = e23.y + el23.y;
            float d0 = q0 - zv0, d1v = q1 - zv1, d2v = q2 - zv2, d3 = q3 - zv3;
            op[(4 * dg + 0) * HT] = zv0 + d0;
            op[(4 * dg + 1) * HT] = zv1 + d1v;
            op[(4 * dg + 2) * HT] = zv2 + d2v;
            op[(4 * dg + 3) * HT] = zv3 + d3;
            csum += d0 * d0 + d1v * d1v + d2v * d2v + d3 * d3;
        }
        if (ahalf == 0) {
            out[ZQ_SIZE + 1 + n] = (float)bi;
            atomicAdd(&g_counts[bi], 1);
        }
        csum_total += csum;

        pbuf ^= 1;   // flip A buffer; no trailing sync needed (next overwrite of this
                     // buffer is two tiles away, ordered by the next tile's barrier)
    }

    // ---------- per-CTA commitment partial ----------
    #pragma unroll
    for (int off = 16; off; off >>= 1)
        csum_total += __shfl_down_sync(0xffffffffu, csum_total, off);
    float* wsum = (float*)(smem + SM_WSUM);
    __syncthreads();   // all tile work done before reusing smem scalars
    if (lid == 0) wsum[wid] = csum_total;
    __syncthreads();
    if (tid == 0) {
        float s = 0.f;
        #pragma unroll
        for (int w = 0; w < 8; w++) s += wsum[w];
        g_part[blockIdx.x] = s;
    }

    // ---------- last-CTA in-kernel finalize ----------
    __threadfence();
    __shared__ int s_last;
    if (tid == 0) s_last = (atomicAdd(&g_done, 1) == GRID - 1);
    __syncthreads();
    if (s_last) {
        __threadfence();
        float* red = (float*)(smem + SM_RED);

        // commitment
        red[tid] = (tid < GRID) ? g_part[tid] : 0.f;
        __syncthreads();
        #pragma unroll
        for (int off = 128; off; off >>= 1) {
            if (tid < off) red[tid] += red[tid + off];
            __syncthreads();
        }
        if (tid == 0) out[ZQ_SIZE] = 0.25f * red[0] / (float)ZQ_SIZE;
        __syncthreads();

        // entropy -> perplexity (512 codes, 2 per thread)
        const int c0 = g_counts[tid], c1 = g_counts[tid + 256];
        {
            float p0 = (float)c0 / (float)N_VEC, p1 = (float)c1 / (float)N_VEC;
            red[tid] = -p0 * logf(p0 + 1e-12f) - p1 * logf(p1 + 1e-12f);
        }
        __syncthreads();
        #pragma unroll
        for (int off = 128; off; off >>= 1) {
            if (tid < off) red[tid] += red[tid + off];
            __syncthreads();
        }
        if (tid == 0) out[ZQ_SIZE + 1 + N_VEC] = expf(red[0]);
        __syncthreads();

        // usage
        red[tid] = ((c0 > 0) ? 1.f : 0.f) + ((c1 > 0) ? 1.f : 0.f);
        __syncthreads();
        #pragma unroll
        for (int off = 128; off; off >>= 1) {
            if (tid < off) red[tid] += red[tid + off];
            __syncthreads();
        }
        if (tid == 0) out[ZQ_SIZE + 1 + N_VEC + 1] = red[0] / (float)NUM_CODES;

        // reset state for next graph replay
        g_counts[tid] = 0;
        g_counts[tid + 256] = 0;
        if (tid == 0) g_done = 0;
    }
}

extern "C" void kernel_launch(void* const* d_in, const int* in_sizes, int n_in,
                              void* d_out, int out_size) {
    const float* z_e   = (const float*)d_in[0];
    const float* embed = (const float*)d_in[1];
    float* out = (float*)d_out;

    cudaFuncSetAttribute(vq_main, cudaFuncAttributeMaxDynamicSharedMemorySize, SMEM_TOTAL);
    vq_main<<<GRID, THREADS, SMEM_TOTAL>>>(z_e, embed, out);
}

// round 17
// speedup vs baseline: 2.3050x; 1.0933x over previous
#include <cuda_runtime.h>
#include <cuda_fp16.h>
#include <cstdint>

#define NUM_CODES 512
#define DIMS      64
#define HT        4096
#define N_VEC     131072
#define ZQ_SIZE   8388608
#define CTA_M     128
#define THREADS   256
#define GRID      148
#define NTILES    1024

// ---- dynamic smem layout (bytes), MMA regions 1024-aligned for SW128 ----
#define SM_AHI   0
#define SM_ALO   16384
#define SM_BHI   32768
#define SM_BLO   98304
#define SM_WSUM  163840
#define SM_RED   163904          // 512 floats for in-kernel finalize
#define SMEM_TOTAL 165952

__device__ float g_part[GRID];        // zero-init; overwritten every call
__device__ int   g_counts[NUM_CODES]; // zero-init; reset by finalize branch
__device__ int   g_done;              // zero-init; reset by finalize branch

#define SW(x) ((x) ^ ((((uint32_t)(x)) >> 3) & 0x70))

__device__ __forceinline__ uint32_t smem_u32(const void* p) {
    uint32_t a;
    asm("{ .reg .u64 t; cvta.to.shared.u64 t, %1; cvt.u32.u64 %0, t; }" : "=r"(a) : "l"(p));
    return a;
}
__device__ __forceinline__ void ldsm_x4(uint32_t& r0, uint32_t& r1, uint32_t& r2, uint32_t& r3, uint32_t a) {
    asm volatile("ldmatrix.sync.aligned.m8n8.x4.shared.b16 {%0,%1,%2,%3}, [%4];"
                 : "=r"(r0), "=r"(r1), "=r"(r2), "=r"(r3) : "r"(a));
}
__device__ __forceinline__ void mma16816(float* c, const uint32_t* a, uint32_t b0, uint32_t b1) {
    asm volatile("mma.sync.aligned.m16n8k16.row.col.f32.f16.f16.f32 "
                 "{%0,%1,%2,%3}, {%4,%5,%6,%7}, {%8,%9}, {%0,%1,%2,%3};"
                 : "+f"(c[0]), "+f"(c[1]), "+f"(c[2]), "+f"(c[3])
                 : "r"(a[0]), "r"(a[1]), "r"(a[2]), "r"(a[3]), "r"(b0), "r"(b1));
}
__device__ __forceinline__ uint32_t h2u(__half2 h) { return reinterpret_cast<uint32_t&>(h); }
__device__ __forceinline__ float2   u2f(uint32_t u) { __half2 h = reinterpret_cast<__half2&>(u); return __half22float2(h); }

__global__ __launch_bounds__(THREADS, 1) void vq_main(
    const float* __restrict__ z_e, const float* __restrict__ embed,
    float* __restrict__ out)
{
    extern __shared__ char smem[];
    const uint32_t sbase = smem_u32(smem);
    const int tid = threadIdx.x, wid = tid >> 5, lid = tid & 31;

    // ---------- B fill ONCE: embedding (512x64 fp32) -> f16 hi/lo, SW128 ----------
    {
        const float4* e4 = (const float4*)embed;
        #pragma unroll 8
        for (int i = tid; i < NUM_CODES * DIMS / 4; i += THREADS) {
            float4 f = e4[i];
            int row = i >> 4, dg = i & 15;
            __half hx = __float2half_rn(f.x), hy = __float2half_rn(f.y);
            __half hz = __float2half_rn(f.z), hw = __float2half_rn(f.w);
            __half lx = __float2half_rn(f.x - __half2float(hx));
            __half ly = __float2half_rn(f.y - __half2float(hy));
            __half lz = __float2half_rn(f.z - __half2float(hz));
            __half lw = __float2half_rn(f.w - __half2float(hw));
            uint32_t off = SW(row * 128 + dg * 8);
            *(uint2*)(smem + SM_BHI + off) = make_uint2(h2u(__halves2half2(hx, hy)), h2u(__halves2half2(hz, hw)));
            *(uint2*)(smem + SM_BLO + off) = make_uint2(h2u(__halves2half2(lx, ly)), h2u(__halves2half2(lz, lw)));
        }
    }
    __syncthreads();   // the ONLY CTA-wide barrier in the tile path (B ready)

    const int rbase = wid * 16;              // one m-tile (16 rows) per warp (warp-local!)
    const int arow = tid >> 1;               // A-fill / epilogue: half row per thread
    const int ahalf = tid & 1;               // dims [ahalf*32, ahalf*32+32)
    const uint32_t brow = ((lid >> 4) << 3) + (lid & 7);
    const uint32_t bk_off = ((lid >> 3) & 1) << 4;
    const int kb = 2 * (lid & 3);
    float csum_total = 0.f;

    // ---------- prefetch first tile's z (half row) into registers ----------
    float zraw[16], zraw2[16], znext[16], znext2[16];
    {
        const int n0 = blockIdx.x * CTA_M + arow;
        const int b0 = n0 >> 12, r0 = n0 & 4095;
        const float* zp0 = z_e + (size_t)b0 * (DIMS * HT) + r0 + (size_t)(ahalf * 32) * HT;
        #pragma unroll
        for (int d = 0; d < 16; d++) {
            zraw[d]  = zp0[(size_t)(2 * d) * HT];
            zraw2[d] = zp0[(size_t)(2 * d + 1) * HT];
        }
    }

    // ================= persistent tile loop (no CTA barriers inside) =================
    for (int tile = blockIdx.x; tile < NTILES; tile += GRID) {
        const int n = tile * CTA_M + arow;
        const int b = n >> 12, r = n & 4095;

        // ---------- A fill from registers -> f16 hi/lo, SW128 (warp-local rows) ----------
        #pragma unroll
        for (int i = 0; i < 4; i++) {
            uint32_t zh[4], zl[4];
            #pragma unroll
            for (int j = 0; j < 4; j++) {
                float x0 = zraw[4 * i + j];
                float x1 = zraw2[4 * i + j];
                __half h0 = __float2half_rn(x0), h1 = __float2half_rn(x1);
                __half l0 = __float2half_rn(x0 - __half2float(h0));
                __half l1 = __float2half_rn(x1 - __half2float(h1));
                zh[j] = h2u(__halves2half2(h0, h1));
                zl[j] = h2u(__halves2half2(l0, l1));
            }
            uint32_t off = SW(arow * 128 + ahalf * 64 + i * 16);
            *(uint4*)(smem + SM_AHI + off) = make_uint4(zh[0], zh[1], zh[2], zh[3]);
            *(uint4*)(smem + SM_ALO + off) = make_uint4(zl[0], zl[1], zl[2], zl[3]);
        }
        __syncwarp();   // STS -> LDSM ordering within the warp

        // ---------- A fragments (this warp's own m-tile) ----------
        uint32_t a_hi[4][4], a_lo[4][4];
        {
            uint32_t row = rbase + ((lid >> 3) & 1) * 8 + (lid & 7);
            uint32_t cg  = (lid >> 4) << 4;
            #pragma unroll
            for (int kt = 0; kt < 4; kt++) {
                uint32_t sw = SW(row * 128 + kt * 32 + cg);
                ldsm_x4(a_hi[kt][0], a_hi[kt][1], a_hi[kt][2], a_hi[kt][3], sbase + SM_AHI + sw);
                ldsm_x4(a_lo[kt][0], a_lo[kt][1], a_lo[kt][2], a_lo[kt][3], sbase + SM_ALO + sw);
            }
        }

        // ---------- issue next tile's z LDGs into znext (hidden under mainloop) ----------
        {
            int ntile = tile + GRID;
            if (ntile >= NTILES) ntile = tile;       // dummy valid address
            const int nn = ntile * CTA_M + arow;
            const int nb = nn >> 12, nr = nn & 4095;
            const float* znp = z_e + (size_t)nb * (DIMS * HT) + nr + (size_t)(ahalf * 32) * HT;
            #pragma unroll
            for (int d = 0; d < 16; d++) {
                znext[d]  = __ldg(znp + (size_t)(2 * d) * HT);
                znext2[d] = __ldg(znp + (size_t)(2 * d + 1) * HT);
            }
        }

        // ---------- main loop: double-buffered accumulators ----------
        float m1[2] = {-3.4e38f, -3.4e38f};
        int   i1[2] = {0, 0};
        float acc0[2][4], acc1[2][4];

#define ZEROACC(A)                                                                 \
        { _Pragma("unroll") for (int h = 0; h < 2; h++)                            \
          _Pragma("unroll") for (int i = 0; i < 4; i++) (A)[h][i] = 0.f; }

#define DOMMA(A, NTP)                                                              \
        { uint32_t B[4][8];                                                        \
          _Pragma("unroll")                                                        \
          for (int kt = 0; kt < 4; kt++) {                                         \
              uint32_t sw = SW((uint32_t)(((NTP) * 16 + brow) * 128 + kt * 32 + bk_off)); \
              ldsm_x4(B[kt][0], B[kt][1], B[kt][2], B[kt][3], sbase + SM_BHI + sw);\
              ldsm_x4(B[kt][4], B[kt][5], B[kt][6], B[kt][7], sbase + SM_BLO + sw);\
          }                                                                        \
          _Pragma("unroll")                                                        \
          for (int kt = 0; kt < 4; kt++) {                                         \
              mma16816((A)[0], a_hi[kt], B[kt][0], B[kt][1]);                      \
              mma16816((A)[1], a_hi[kt], B[kt][2], B[kt][3]);                      \
              mma16816((A)[0], a_hi[kt], B[kt][4], B[kt][5]);                      \
              mma16816((A)[1], a_hi[kt], B[kt][6], B[kt][7]);                      \
              mma16816((A)[0], a_lo[kt], B[kt][0], B[kt][1]);                      \
              mma16816((A)[1], a_lo[kt], B[kt][2], B[kt][3]);                      \
          } }

#define TRACK(A, NTP)                                                              \
        { const int kbase = (NTP) * 16 + kb;                                       \
          _Pragma("unroll") for (int h = 0; h < 2; h++)                            \
          _Pragma("unroll") for (int i = 0; i < 4; i++) {                          \
              int s = i >> 1;                                                      \
              int k = kbase + h * 8 + (i & 1);                                     \
              float dot = (A)[h][i];                                               \
              if (dot > m1[s]) { m1[s] = dot; i1[s] = k; }                         \
          } }

        ZEROACC(acc0);
        DOMMA(acc0, 0);
        #pragma unroll 2
        for (int ntpp = 0; ntpp < 15; ntpp++) {
            const int e = 2 * ntpp;
            ZEROACC(acc1);
            DOMMA(acc1, e + 1);
            TRACK(acc0, e);
            ZEROACC(acc0);
            DOMMA(acc0, e + 2);
            TRACK(acc1, e + 1);
        }
        ZEROACC(acc1);
        DOMMA(acc1, 31);
        TRACK(acc0, 30);
        TRACK(acc1, 31);

        // ---------- merge max(dot) across the 4 quad lanes ----------
        #pragma unroll
        for (int off = 1; off <= 2; off <<= 1) {
            #pragma unroll
            for (int s = 0; s < 2; s++) {
                float om = __shfl_xor_sync(0xffffffffu, m1[s], off);
                int   oi = __shfl_xor_sync(0xffffffffu, i1[s], off);
                bool take = (om > m1[s]) || (om == m1[s] && oi < i1[s]);
                if (take) { m1[s] = om; i1[s] = oi; }
            }
        }
        // shuffle-based bi for this thread's row (same warp owns it)
        int bi;
        {
            const int rr = (tid >> 1) & 15;          // row within this warp's m-tile
            const int src = 4 * (rr & 7);
            int v0 = __shfl_sync(0xffffffffu, i1[0], src);
            int v1 = __shfl_sync(0xffffffffu, i1[1], src);
            bi = (rr >> 3) ? v1 : v0;
        }

        // ---------- outputs: exact z from registers, q from B smem ----------
        float* op = out + (size_t)b * (DIMS * HT) + r + (size_t)(ahalf * 32) * HT;
        float csum = 0.f;
        #pragma unroll
        for (int dg = 0; dg < 8; dg++) {
            float zv0 = zraw[2 * dg],     zv1 = zraw2[2 * dg];
            float zv2 = zraw[2 * dg + 1], zv3 = zraw2[2 * dg + 1];
            uint32_t qo = SW(bi * 128 + ahalf * 64 + dg * 8);
            uint2 qh = *(uint2*)(smem + SM_BHI + qo);
            uint2 ql = *(uint2*)(smem + SM_BLO + qo);
            float2 e01 = u2f(qh.x), el01 = u2f(ql.x), e23 = u2f(qh.y), el23 = u2f(ql.y);
            float q0 = e01.x + el01.x, q1 = e01.y + el01.y, q2 = e23.x + el23.x, q3 = e23.y + el23.y;
            float d0 = q0 - zv0, d1v = q1 - zv1, d2v = q2 - zv2, d3 = q3 - zv3;
            op[(4 * dg + 0) * HT] = zv0 + d0;
            op[(4 * dg + 1) * HT] = zv1 + d1v;
            op[(4 * dg + 2) * HT] = zv2 + d2v;
            op[(4 * dg + 3) * HT] = zv3 + d3;
            csum += d0 * d0 + d1v * d1v + d2v * d2v + d3 * d3;
        }
        if (ahalf == 0) {
            out[ZQ_SIZE + 1 + n] = (float)bi;
            atomicAdd(&g_counts[bi], 1);
        }
        csum_total += csum;

        // rotate prefetched z into place (register copies)
        #pragma unroll
        for (int d = 0; d < 16; d++) { zraw[d] = znext[d]; zraw2[d] = znext2[d]; }
    }

    // ---------- per-CTA commitment partial ----------
    #pragma unroll
    for (int off = 16; off; off >>= 1)
        csum_total += __shfl_down_sync(0xffffffffu, csum_total, off);
    float* wsum = (float*)(smem + SM_WSUM);
    __syncthreads();   // re-converge all warps before smem scalar reuse
    if (lid == 0) wsum[wid] = csum_total;
    __syncthreads();
    if (tid == 0) {
        float s = 0.f;
        #pragma unroll
        for (int w = 0; w < 8; w++) s += wsum[w];
        g_part[blockIdx.x] = s;
    }

    // ---------- last-CTA in-kernel finalize ----------
    __threadfence();
    __shared__ int s_last;
    if (tid == 0) s_last = (atomicAdd(&g_done, 1) == GRID - 1);
    __syncthreads();
    if (s_last) {
        __threadfence();
        float* red = (float*)(smem + SM_RED);

        // commitment
        red[tid] = (tid < GRID) ? g_part[tid] : 0.f;
        __syncthreads();
        #pragma unroll
        for (int off = 128; off; off >>= 1) {
            if (tid < off) red[tid] += red[tid + off];
            __syncthreads();
        }
        if (tid == 0) out[ZQ_SIZE] = 0.25f * red[0] / (float)ZQ_SIZE;
        __syncthreads();

        // entropy -> perplexity (512 codes, 2 per thread)
        const int c0 = g_counts[tid], c1 = g_counts[tid + 256];
        {
            float p0 = (float)c0 / (float)N_VEC, p1 = (float)c1 / (float)N_VEC;
            red[tid] = -p0 * logf(p0 + 1e-12f) - p1 * logf(p1 + 1e-12f);
        }
        __syncthreads();
        #pragma unroll
        for (int off = 128; off; off >>= 1) {
            if (tid < off) red[tid] += red[tid + off];
            __syncthreads();
        }
        if (tid == 0) out[ZQ_SIZE + 1 + N_VEC] = expf(red[0]);
        __syncthreads();

        // usage
        red[tid] = ((c0 > 0) ? 1.f : 0.f) + ((c1 > 0) ? 1.f : 0.f);
        __syncthreads();
        #pragma unroll
        for (int off = 128; off; off >>= 1) {
            if (tid < off) red[tid] += red[tid + off];
            __syncthreads();
        }
        if (tid == 0) out[ZQ_SIZE + 1 + N_VEC + 1] = red[0] / (float)NUM_CODES;

        // reset state for next graph replay
        g_counts[tid] = 0;
        g_counts[tid + 256] = 0;
        if (tid == 0) g_done = 0;
    }
}

extern "C" void kernel_launch(void* const* d_in, const int* in_sizes, int n_in,
                              void* d_out, int out_size) {
    const float* z_e   = (const float*)d_in[0];
    const float* embed = (const float*)d_in[1];
    float* out = (float*)d_out;

    cudaFuncSetAttribute(vq_main, cudaFuncAttributeMaxDynamicSharedMemorySize, SMEM_TOTAL);
    vq_main<<<GRID, THREADS, SMEM_TOTAL>>>(z_e, embed, out);
}